// round 15
// baseline (speedup 1.0000x reference)
#include <cuda_runtime.h>
#include <cuda_bf16.h>
#include <cuda_fp16.h>
#include <stdint.h>
#include <math.h>

// ---------------------------------------------------------------------------
// Problem constants
// ---------------------------------------------------------------------------
#define NB   8192
#define NT   8192
#define FD   768
#define PD   512
#define HD   1024
#define NE   4
#define TWOP 1024
#define RHD  256

#define DS_OFF  (8192ull*8192ull)
#define PR_OFF  (8192ull*8192ull + 8192ull)

typedef unsigned long long u64;

// ---------------------------------------------------------------------------
// Scratch (device globals: allocation-free)
// ---------------------------------------------------------------------------
__device__ __nv_bfloat16 g_th [8192ull*768],  g_tl [8192ull*768];
__device__ __nv_bfloat16 g_ih [8192ull*768],  g_il [8192ull*768];
__device__ __nv_bfloat16 g_Wth[512*768],      g_Wtl[512*768];
__device__ __nv_bfloat16 g_Wih[512*768],      g_Wil[512*768];
__device__ __nv_bfloat16 g_rWh[256*1024],     g_rWl[256*1024];
__device__ __nv_bfloat16 g_eWh[4096ull*1024], g_eWl[4096ull*1024];
__device__ __nv_bfloat16 g_dWh[1024ull*1024], g_dWl[1024ull*1024];
__device__ __nv_bfloat16 g_oWh[768*1024],     g_oWl[768*1024];
__device__ __nv_bfloat16 g_cbh[8192ull*1024], g_cbl[8192ull*1024];
__device__ __nv_bfloat16 g_fuh[8192ull*1024], g_ful[8192ull*1024];
__device__ __half        g_prf[8192ull*768];   // pred, fp16 (logits GEMM A)
__device__ __half        g_tgf[8192ull*768];   // tgt,  fp16 (logits GEMM B)
__device__ float g_rh   [8192ull*256];
__device__ float g_eo   [8192ull*4096];
__device__ float g_dh   [8192ull*1024];
__device__ float g_resid[8192ull*768];
__device__ float g_probs[8192ull*4];
__device__ float g_ds   [8192];

// ---------------------------------------------------------------------------
// Generic-ISA helpers (sm_80-level: ldmatrix / mma.sync / cp.async only)
// ---------------------------------------------------------------------------
__device__ __forceinline__ uint32_t smem_u32(const void* p) {
    uint32_t a;
    asm("{ .reg .u64 t; cvta.to.shared.u64 t, %1; cvt.u32.u64 %0, t; }"
        : "=r"(a) : "l"(p));
    return a;
}

__device__ __forceinline__ void ldsm4(uint32_t* r, uint32_t addr) {
    asm volatile("ldmatrix.sync.aligned.m8n8.x4.shared.b16 {%0,%1,%2,%3}, [%4];"
        : "=r"(r[0]), "=r"(r[1]), "=r"(r[2]), "=r"(r[3]) : "r"(addr));
}

__device__ __forceinline__ void mma16816(float* c, const uint32_t* a, const uint32_t* b) {
    asm volatile(
        "mma.sync.aligned.m16n8k16.row.col.f32.bf16.bf16.f32 "
        "{%0,%1,%2,%3},{%4,%5,%6,%7},{%8,%9},{%0,%1,%2,%3};"
        : "+f"(c[0]), "+f"(c[1]), "+f"(c[2]), "+f"(c[3])
        : "r"(a[0]), "r"(a[1]), "r"(a[2]), "r"(a[3]), "r"(b[0]), "r"(b[1]));
}

__device__ __forceinline__ void mma16816h(float* c, const uint32_t* a, const uint32_t* b) {
    asm volatile(
        "mma.sync.aligned.m16n8k16.row.col.f32.f16.f16.f32 "
        "{%0,%1,%2,%3},{%4,%5,%6,%7},{%8,%9},{%0,%1,%2,%3};"
        : "+f"(c[0]), "+f"(c[1]), "+f"(c[2]), "+f"(c[3])
        : "r"(a[0]), "r"(a[1]), "r"(a[2]), "r"(a[3]), "r"(b[0]), "r"(b[1]));
}

__device__ __forceinline__ void cp16(uint32_t saddr, const void* gptr) {
    asm volatile("cp.async.cg.shared.global [%0], [%1], 16;"
        :: "r"(saddr), "l"(gptr));
}
#define CP_COMMIT() asm volatile("cp.async.commit_group;")
#define CP_WAIT0()  asm volatile("cp.async.wait_group 0;")
#define CP_WAIT1()  asm volatile("cp.async.wait_group 1;")

__device__ __forceinline__ float gelu_exact(float x) {
    return 0.5f * x * (1.0f + erff(x * 0.70710678118654752440f));
}
__device__ __forceinline__ void split2(float x, __nv_bfloat16& h, __nv_bfloat16& l) {
    h = __float2bfloat16(x);
    l = __float2bfloat16(x - __bfloat162float(h));
}

// ---------------------------------------------------------------------------
// Split-bf16 HMMA GEMM: C[M,N] = epi( (Ah+Al)[M,K] @ (Bh+Bl)[N,K]^T )
//   via mma.sync m16n8k16 (hh + hl + lh products, fp32 accum).
// CTA 128x256, 8 warps (warp tile 64x64, grid 2x4), BK=32,
// cp.async 3-stage pipeline (wait_group 1 steady-state).
// Smem per buffer (48KB): Ah@0(8K) Al@8K Bh@16K(16K) Bl@32K(16K).
// Row = 64B (32 bf16), 16B-chunk swizzle: chunk' = chunk ^ ((row>>1)&3).
// EPI: 0 = gelu(acc+bias[n]), 1 = acc+bias[n]
// OUT: 0 = fp32 C, 1 = split-bf16 (Ch, Cl)
// ---------------------------------------------------------------------------
#define BUFSZ 49152
#define GEMM_SMEM (3 * BUFSZ + 128)

template <int EPI, int OUT>
__global__ __launch_bounds__(256, 1) void gemm_mma(
    const __nv_bfloat16* __restrict__ Ah, const __nv_bfloat16* __restrict__ Al,
    const __nv_bfloat16* __restrict__ Bh, const __nv_bfloat16* __restrict__ Bl,
    float* __restrict__ C, __nv_bfloat16* __restrict__ Ch, __nv_bfloat16* __restrict__ Cl,
    int K, int ldc, int coloff,
    const float* __restrict__ bias)
{
    extern __shared__ char smraw[];
    const uint32_t sbase = (smem_u32(smraw) + 127u) & ~127u;

    const int tid  = threadIdx.x;
    const int wid  = tid >> 5;
    const int lane = tid & 31;
    const int wm   = wid >> 2;       // 0..1  (M: 64 rows)
    const int wn   = wid & 3;        // 0..3  (N: 64 cols)
    const int bm   = blockIdx.y * 128;
    const int bn   = blockIdx.x * 256;

    float acc[4][8][4];
    #pragma unroll
    for (int i = 0; i < 4; i++)
        #pragma unroll
        for (int j = 0; j < 8; j++)
            #pragma unroll
            for (int r = 0; r < 4; r++) acc[i][j][r] = 0.f;

    const __nv_bfloat16* srcAh = Ah + (u64)bm * K;
    const __nv_bfloat16* srcAl = Al + (u64)bm * K;
    const __nv_bfloat16* srcBh = Bh + (u64)bn * K;
    const __nv_bfloat16* srcBl = Bl + (u64)bn * K;

    const int srow = tid >> 2;
    const int sc   = tid & 3;
    const uint32_t sw0 = (uint32_t)(srow * 64 + ((sc ^ ((srow >> 1) & 3)) << 4));
    const int gcol = sc * 8;

    const int rA  = lane & 15;
    const int cAx = (lane >> 4) & 1;
    const int nB  = (lane & 7) | (((lane >> 4) & 1) << 3);
    const int cBx = (lane >> 3) & 1;

    const int nchunk = K >> 5;

#define LOAD_CHUNK(KB, BUFB) do {                                                   \
        const int _kb = (KB); const uint32_t _bb = (BUFB);                          \
        _Pragma("unroll")                                                           \
        for (int p = 0; p < 2; p++) {                                               \
            const u64 go = (u64)(srow + p * 64) * K + _kb + gcol;                   \
            cp16(_bb +        p * 4096 + sw0, srcAh + go);                          \
            cp16(_bb + 8192 + p * 4096 + sw0, srcAl + go);                          \
        }                                                                           \
        _Pragma("unroll")                                                           \
        for (int p = 0; p < 4; p++) {                                               \
            const u64 go = (u64)(srow + p * 64) * K + _kb + gcol;                   \
            cp16(_bb + 16384 + p * 4096 + sw0, srcBh + go);                         \
            cp16(_bb + 32768 + p * 4096 + sw0, srcBl + go);                         \
        }                                                                           \
        CP_COMMIT();                                                                \
    } while (0)

    LOAD_CHUNK(0, sbase);
    if (nchunk > 1) LOAD_CHUNK(32, sbase + BUFSZ);

    for (int i = 0; i < nchunk; i++) {
        if (i == nchunk - 1) { CP_WAIT0(); } else { CP_WAIT1(); }
        __syncthreads();
        if (i + 2 < nchunk)
            LOAD_CHUNK((i + 2) << 5, sbase + (uint32_t)(((i + 2) % 3) * BUFSZ));

        const uint32_t bufb = sbase + (uint32_t)((i % 3) * BUFSZ);
        #pragma unroll
        for (int ks = 0; ks < 2; ks++) {
            uint32_t a[4][4], bh[8][2], bl[8][2], t4[4];
            #pragma unroll
            for (int am = 0; am < 4; am++) {
                const int row = wm * 64 + am * 16 + rA;
                const int c   = ks * 2 + cAx;
                ldsm4(a[am], bufb + row * 64 + (uint32_t)((c ^ ((row >> 1) & 3)) << 4));
            }
            #pragma unroll
            for (int np = 0; np < 4; np++) {
                const int row = wn * 64 + np * 16 + nB;
                const int c   = ks * 2 + cBx;
                ldsm4(t4, bufb + 16384 + row * 64 + (uint32_t)((c ^ ((row >> 1) & 3)) << 4));
                bh[np*2][0] = t4[0]; bh[np*2][1] = t4[1];
                bh[np*2+1][0] = t4[2]; bh[np*2+1][1] = t4[3];
            }
            #pragma unroll
            for (int np = 0; np < 4; np++) {
                const int row = wn * 64 + np * 16 + nB;
                const int c   = ks * 2 + cBx;
                ldsm4(t4, bufb + 32768 + row * 64 + (uint32_t)((c ^ ((row >> 1) & 3)) << 4));
                bl[np*2][0] = t4[0]; bl[np*2][1] = t4[1];
                bl[np*2+1][0] = t4[2]; bl[np*2+1][1] = t4[3];
            }
            #pragma unroll
            for (int am = 0; am < 4; am++)
                #pragma unroll
                for (int an = 0; an < 8; an++)
                    mma16816(acc[am][an], a[am], bh[an]);
            #pragma unroll
            for (int am = 0; am < 4; am++)
                #pragma unroll
                for (int an = 0; an < 8; an++)
                    mma16816(acc[am][an], a[am], bl[an]);
            #pragma unroll
            for (int am = 0; am < 4; am++) {
                const int row = wm * 64 + am * 16 + rA;
                const int c   = ks * 2 + cAx;
                ldsm4(a[am], bufb + 8192 + row * 64 + (uint32_t)((c ^ ((row >> 1) & 3)) << 4));
            }
            #pragma unroll
            for (int am = 0; am < 4; am++)
                #pragma unroll
                for (int an = 0; an < 8; an++)
                    mma16816(acc[am][an], a[am], bh[an]);
        }
        __syncthreads();
    }
#undef LOAD_CHUNK

    const int g  = lane >> 2;
    const int tg = lane & 3;
    #pragma unroll
    for (int am = 0; am < 4; am++) {
        const int row0 = bm + wm * 64 + am * 16 + g;
        #pragma unroll
        for (int an = 0; an < 8; an++) {
            const int coln = wn * 64 + an * 8 + tg * 2;
            float v[4];
            #pragma unroll
            for (int r = 0; r < 4; r++) {
                float x = acc[am][an][r];
                const int n = bn + coln + (r & 1);
                if (EPI == 0)      x = gelu_exact(x + __ldg(bias + n));
                else               x = x + __ldg(bias + n);
                v[r] = x;
            }
            if (OUT == 0) {
                *(float2*)(C + (u64)row0 * ldc + coloff + bn + coln)       = make_float2(v[0], v[1]);
                *(float2*)(C + (u64)(row0 + 8) * ldc + coloff + bn + coln) = make_float2(v[2], v[3]);
            } else {
                __nv_bfloat16 h0,l0,h1,l1;
                split2(v[0], h0, l0); split2(v[1], h1, l1);
                __nv_bfloat162 H0; H0.x = h0; H0.y = h1;
                __nv_bfloat162 L0; L0.x = l0; L0.y = l1;
                *(__nv_bfloat162*)(Ch + (u64)row0 * ldc + coloff + bn + coln) = H0;
                *(__nv_bfloat162*)(Cl + (u64)row0 * ldc + coloff + bn + coln) = L0;
                split2(v[2], h0, l0); split2(v[3], h1, l1);
                H0.x = h0; H0.y = h1; L0.x = l0; L0.y = l1;
                *(__nv_bfloat162*)(Ch + (u64)(row0 + 8) * ldc + coloff + bn + coln) = H0;
                *(__nv_bfloat162*)(Cl + (u64)(row0 + 8) * ldc + coloff + bn + coln) = L0;
            }
        }
    }
}

// ---------------------------------------------------------------------------
// Plain-fp16 HMMA GEMM for the logits: C = exp(*scale_p) * (A @ B^T)
// Single product; CTA 128x256, BK=32, 3-stage pipeline.
// Smem per buffer (24KB): A@0(8K) B@8K(16K). Same 64B rows / swizzle.
// ---------------------------------------------------------------------------
#define FBUFSZ 24576
#define FP16_SMEM (3 * FBUFSZ + 128)

__global__ __launch_bounds__(256, 1) void gemm_fp16(
    const __half* __restrict__ A, const __half* __restrict__ B,
    float* __restrict__ C, int K, int ldc,
    const float* __restrict__ scale_p)
{
    extern __shared__ char smraw[];
    const uint32_t sbase = (smem_u32(smraw) + 127u) & ~127u;

    const int tid  = threadIdx.x;
    const int wid  = tid >> 5;
    const int lane = tid & 31;
    const int wm   = wid >> 2;
    const int wn   = wid & 3;
    const int bm   = blockIdx.y * 128;
    const int bn   = blockIdx.x * 256;

    float acc[4][8][4];
    #pragma unroll
    for (int i = 0; i < 4; i++)
        #pragma unroll
        for (int j = 0; j < 8; j++)
            #pragma unroll
            for (int r = 0; r < 4; r++) acc[i][j][r] = 0.f;

    const __half* srcA = A + (u64)bm * K;
    const __half* srcB = B + (u64)bn * K;

    const int srow = tid >> 2;
    const int sc   = tid & 3;
    const uint32_t sw0 = (uint32_t)(srow * 64 + ((sc ^ ((srow >> 1) & 3)) << 4));
    const int gcol = sc * 8;

    const int rA  = lane & 15;
    const int cAx = (lane >> 4) & 1;
    const int nB  = (lane & 7) | (((lane >> 4) & 1) << 3);
    const int cBx = (lane >> 3) & 1;

    const int nchunk = K >> 5;

#define LOAD_CHUNK_F(KB, BUFB) do {                                                 \
        const int _kb = (KB); const uint32_t _bb = (BUFB);                          \
        _Pragma("unroll")                                                           \
        for (int p = 0; p < 2; p++)                                                 \
            cp16(_bb + p * 4096 + sw0, srcA + (u64)(srow + p * 64) * K + _kb + gcol); \
        _Pragma("unroll")                                                           \
        for (int p = 0; p < 4; p++)                                                 \
            cp16(_bb + 8192 + p * 4096 + sw0, srcB + (u64)(srow + p * 64) * K + _kb + gcol); \
        CP_COMMIT();                                                                \
    } while (0)

    LOAD_CHUNK_F(0, sbase);
    if (nchunk > 1) LOAD_CHUNK_F(32, sbase + FBUFSZ);

    for (int i = 0; i < nchunk; i++) {
        if (i == nchunk - 1) { CP_WAIT0(); } else { CP_WAIT1(); }
        __syncthreads();
        if (i + 2 < nchunk)
            LOAD_CHUNK_F((i + 2) << 5, sbase + (uint32_t)(((i + 2) % 3) * FBUFSZ));

        const uint32_t bufb = sbase + (uint32_t)((i % 3) * FBUFSZ);
        #pragma unroll
        for (int ks = 0; ks < 2; ks++) {
            uint32_t a[4][4], bb[8][2], t4[4];
            #pragma unroll
            for (int am = 0; am < 4; am++) {
                const int row = wm * 64 + am * 16 + rA;
                const int c   = ks * 2 + cAx;
                ldsm4(a[am], bufb + row * 64 + (uint32_t)((c ^ ((row >> 1) & 3)) << 4));
            }
            #pragma unroll
            for (int np = 0; np < 4; np++) {
                const int row = wn * 64 + np * 16 + nB;
                const int c   = ks * 2 + cBx;
                ldsm4(t4, bufb + 8192 + row * 64 + (uint32_t)((c ^ ((row >> 1) & 3)) << 4));
                bb[np*2][0] = t4[0]; bb[np*2][1] = t4[1];
                bb[np*2+1][0] = t4[2]; bb[np*2+1][1] = t4[3];
            }
            #pragma unroll
            for (int am = 0; am < 4; am++)
                #pragma unroll
                for (int an = 0; an < 8; an++)
                    mma16816h(acc[am][an], a[am], bb[an]);
        }
        __syncthreads();
    }
#undef LOAD_CHUNK_F

    const float scale = expf(*scale_p);
    const int g  = lane >> 2;
    const int tg = lane & 3;
    #pragma unroll
    for (int am = 0; am < 4; am++) {
        const int row0 = bm + wm * 64 + am * 16 + g;
        #pragma unroll
        for (int an = 0; an < 8; an++) {
            const int coln = wn * 64 + an * 8 + tg * 2;
            float* c0 = C + (u64)row0 * ldc + bn + coln;
            float* c1 = C + (u64)(row0 + 8) * ldc + bn + coln;
            *(float2*)c0 = make_float2(acc[am][an][0] * scale, acc[am][an][1] * scale);
            *(float2*)c1 = make_float2(acc[am][an][2] * scale, acc[am][an][3] * scale);
        }
    }
}

// ---------------------------------------------------------------------------
// fp32 -> split bf16 (hi, lo), vectorized x4
// ---------------------------------------------------------------------------
__global__ void split_kernel(const float* __restrict__ in,
                             __nv_bfloat16* __restrict__ h,
                             __nv_bfloat16* __restrict__ l, int n4)
{
    int i = blockIdx.x * blockDim.x + threadIdx.x;
    if (i >= n4) return;
    float4 v = ((const float4*)in)[i];
    __nv_bfloat16 h0,l0,h1,l1,h2,l2,h3,l3;
    split2(v.x, h0, l0); split2(v.y, h1, l1);
    split2(v.z, h2, l2); split2(v.w, h3, l3);
    __nv_bfloat162 H0; H0.x = h0; H0.y = h1;
    __nv_bfloat162 H1; H1.x = h2; H1.y = h3;
    __nv_bfloat162 L0; L0.x = l0; L0.y = l1;
    __nv_bfloat162 L1; L1.x = l2; L1.y = l3;
    ((__nv_bfloat162*)h)[2*i]   = H0;
    ((__nv_bfloat162*)h)[2*i+1] = H1;
    ((__nv_bfloat162*)l)[2*i]   = L0;
    ((__nv_bfloat162*)l)[2*i+1] = L1;
}

// ---------------------------------------------------------------------------
// Router: logits = rh @ rt_W2^T + b2 ; softmax. One warp per row.
// ---------------------------------------------------------------------------
__global__ void router_kernel(const float* __restrict__ rh,
                              const float* __restrict__ W2,
                              const float* __restrict__ b2,
                              float* __restrict__ probs,
                              float* __restrict__ out_probs)
{
    int warp = (blockIdx.x * blockDim.x + threadIdx.x) >> 5;
    int lane = threadIdx.x & 31;
    if (warp >= NB) return;
    const float* r = rh + (u64)warp * RHD;
    float s0 = 0.f, s1 = 0.f, s2 = 0.f, s3 = 0.f;
    #pragma unroll
    for (int i = 0; i < RHD / 32; i++) {
        int c = lane + i * 32;
        float v = r[c];
        s0 += v * W2[c];
        s1 += v * W2[RHD + c];
        s2 += v * W2[2 * RHD + c];
        s3 += v * W2[3 * RHD + c];
    }
    #pragma unroll
    for (int o = 16; o > 0; o >>= 1) {
        s0 += __shfl_xor_sync(0xffffffffu, s0, o);
        s1 += __shfl_xor_sync(0xffffffffu, s1, o);
        s2 += __shfl_xor_sync(0xffffffffu, s2, o);
        s3 += __shfl_xor_sync(0xffffffffu, s3, o);
    }
    if (lane == 0) {
        float l0 = s0 + b2[0], l1 = s1 + b2[1], l2 = s2 + b2[2], l3 = s3 + b2[3];
        float m  = fmaxf(fmaxf(l0, l1), fmaxf(l2, l3));
        float e0 = expf(l0 - m), e1 = expf(l1 - m), e2 = expf(l2 - m), e3 = expf(l3 - m);
        float inv = 1.f / (e0 + e1 + e2 + e3);
        float4 p = make_float4(e0 * inv, e1 * inv, e2 * inv, e3 * inv);
        *(float4*)(probs + (u64)warp * 4) = p;
        *(float4*)(out_probs + (u64)warp * 4) = p;
    }
}

// ---------------------------------------------------------------------------
// ds = sigmoid(dh . W2 + b2). One warp per row.
// ---------------------------------------------------------------------------
__global__ void ds_kernel(const float* __restrict__ dh,
                          const float* __restrict__ W2,
                          const float* __restrict__ b2,
                          float* __restrict__ ds,
                          float* __restrict__ out_ds)
{
    int warp = (blockIdx.x * blockDim.x + threadIdx.x) >> 5;
    int lane = threadIdx.x & 31;
    if (warp >= NB) return;
    const float* r = dh + (u64)warp * HD;
    float s = 0.f;
    #pragma unroll
    for (int i = 0; i < HD / 32; i++) s += r[lane + i * 32] * W2[lane + i * 32];
    #pragma unroll
    for (int o = 16; o > 0; o >>= 1) s += __shfl_xor_sync(0xffffffffu, s, o);
    if (lane == 0) {
        float sg = 1.f / (1.f + expf(-(s + b2[0])));
        ds[warp] = sg;
        out_ds[warp] = sg;
    }
}

// ---------------------------------------------------------------------------
// fused[b,h] = sum_e probs[b,e]*eo[b,e*H+h] -> split bf16 out
// ---------------------------------------------------------------------------
__global__ void expert_reduce_kernel(const float* __restrict__ eo,
                                     const float* __restrict__ probs,
                                     __nv_bfloat16* __restrict__ fh,
                                     __nv_bfloat16* __restrict__ fl)
{
    u64 idx = (u64)blockIdx.x * blockDim.x + threadIdx.x;
    if (idx >= (u64)NB * HD) return;
    u64 b = idx >> 10;
    u64 h = idx & 1023u;
    const float* p = probs + b * 4;
    const float* e = eo + b * (u64)(NE * HD) + h;
    float v = p[0]*e[0] + p[1]*e[HD] + p[2]*e[2*HD] + p[3]*e[3*HD];
    __nv_bfloat16 hh, ll;
    split2(v, hh, ll);
    fh[idx] = hh; fl[idx] = ll;
}

// ---------------------------------------------------------------------------
// pred = normalize(ds*text + (1-ds)*image + resid) -> fp16
// ---------------------------------------------------------------------------
__global__ __launch_bounds__(256) void fuse_norm_kernel(
    const float* __restrict__ resid, const float* __restrict__ text,
    const float* __restrict__ image, const float* __restrict__ ds,
    __half* __restrict__ pf)
{
    __shared__ float red[8];
    const int b = blockIdx.x;
    const int t = threadIdx.x;
    const float d = ds[b];
    float v[3];
    float ss = 0.f;
    #pragma unroll
    for (int q = 0; q < 3; q++) {
        u64 off = (u64)b * FD + t + q * 256;
        float val = d * text[off] + (1.f - d) * image[off] + resid[off];
        v[q] = val;
        ss += val * val;
    }
    #pragma unroll
    for (int o = 16; o > 0; o >>= 1) ss += __shfl_xor_sync(0xffffffffu, ss, o);
    if ((t & 31) == 0) red[t >> 5] = ss;
    __syncthreads();
    if (t < 32) {
        float x = (t < 8) ? red[t] : 0.f;
        #pragma unroll
        for (int o = 4; o > 0; o >>= 1) x += __shfl_xor_sync(0xffffffffu, x, o);
        if (t == 0) red[0] = x;
    }
    __syncthreads();
    const float inv = 1.f / fmaxf(sqrtf(red[0]), 1e-12f);
    #pragma unroll
    for (int q = 0; q < 3; q++) {
        u64 off = (u64)b * FD + t + q * 256;
        pf[off] = __float2half(v[q] * inv);
    }
}

// ---------------------------------------------------------------------------
// tgt = normalize(target) -> fp16
// ---------------------------------------------------------------------------
__global__ __launch_bounds__(256) void norm_kernel(const float* __restrict__ in,
                                                   __half* __restrict__ tf)
{
    __shared__ float red[8];
    const int b = blockIdx.x;
    const int t = threadIdx.x;
    float v[3];
    float ss = 0.f;
    #pragma unroll
    for (int q = 0; q < 3; q++) {
        float val = in[(u64)b * FD + t + q * 256];
        v[q] = val;
        ss += val * val;
    }
    #pragma unroll
    for (int o = 16; o > 0; o >>= 1) ss += __shfl_xor_sync(0xffffffffu, ss, o);
    if ((t & 31) == 0) red[t >> 5] = ss;
    __syncthreads();
    if (t < 32) {
        float x = (t < 8) ? red[t] : 0.f;
        #pragma unroll
        for (int o = 4; o > 0; o >>= 1) x += __shfl_xor_sync(0xffffffffu, x, o);
        if (t == 0) red[0] = x;
    }
    __syncthreads();
    const float inv = 1.f / fmaxf(sqrtf(red[0]), 1e-12f);
    #pragma unroll
    for (int q = 0; q < 3; q++) {
        u64 off = (u64)b * FD + t + q * 256;
        tf[off] = __float2half(v[q] * inv);
    }
}

// ---------------------------------------------------------------------------
// Launch
// ---------------------------------------------------------------------------
static inline void launch_split(const float* src, __nv_bfloat16* h,
                                __nv_bfloat16* l, u64 n) {
    int n4 = (int)(n >> 2);
    split_kernel<<<(n4 + 255) / 256, 256>>>(src, h, l, n4);
}

extern "C" void kernel_launch(void* const* d_in, const int* in_sizes, int n_in,
                              void* d_out, int out_size)
{
    const float* image  = (const float*)d_in[0];
    const float* text   = (const float*)d_in[1];
    const float* target = (const float*)d_in[2];
    const float* Wt     = (const float*)d_in[3];
    const float* bt     = (const float*)d_in[4];
    const float* Wi     = (const float*)d_in[5];
    const float* bi     = (const float*)d_in[6];
    const float* dsW1   = (const float*)d_in[7];
    const float* dsb1   = (const float*)d_in[8];
    const float* dsW2   = (const float*)d_in[9];
    const float* dsb2   = (const float*)d_in[10];
    const float* expW   = (const float*)d_in[11];
    const float* expb   = (const float*)d_in[12];
    const float* rtW1   = (const float*)d_in[13];
    const float* rtb1   = (const float*)d_in[14];
    const float* rtW2   = (const float*)d_in[15];
    const float* rtb2   = (const float*)d_in[16];
    const float* outW   = (const float*)d_in[17];
    const float* outb   = (const float*)d_in[18];
    const float* lscale = (const float*)d_in[19];
    float* out = (float*)d_out;

    __nv_bfloat16 *th,*tl,*ih,*il,*Wth,*Wtl,*Wih,*Wil,*rWh,*rWl,*eWh,*eWl;
    __nv_bfloat16 *dWh,*dWl,*oWh,*oWl,*cbh,*cbl,*fuh,*ful;
    __half *prf,*tgf;
    float *rh,*eo,*dh,*resid,*probs,*dsv;
    cudaGetSymbolAddress((void**)&th,  g_th);  cudaGetSymbolAddress((void**)&tl,  g_tl);
    cudaGetSymbolAddress((void**)&ih,  g_ih);  cudaGetSymbolAddress((void**)&il,  g_il);
    cudaGetSymbolAddress((void**)&Wth, g_Wth); cudaGetSymbolAddress((void**)&Wtl, g_Wtl);
    cudaGetSymbolAddress((void**)&Wih, g_Wih); cudaGetSymbolAddress((void**)&Wil, g_Wil);
    cudaGetSymbolAddress((void**)&rWh, g_rWh); cudaGetSymbolAddress((void**)&rWl, g_rWl);
    cudaGetSymbolAddress((void**)&eWh, g_eWh); cudaGetSymbolAddress((void**)&eWl, g_eWl);
    cudaGetSymbolAddress((void**)&dWh, g_dWh); cudaGetSymbolAddress((void**)&dWl, g_dWl);
    cudaGetSymbolAddress((void**)&oWh, g_oWh); cudaGetSymbolAddress((void**)&oWl, g_oWl);
    cudaGetSymbolAddress((void**)&cbh, g_cbh); cudaGetSymbolAddress((void**)&cbl, g_cbl);
    cudaGetSymbolAddress((void**)&fuh, g_fuh); cudaGetSymbolAddress((void**)&ful, g_ful);
    cudaGetSymbolAddress((void**)&prf, g_prf); cudaGetSymbolAddress((void**)&tgf, g_tgf);
    cudaGetSymbolAddress((void**)&rh,    g_rh);
    cudaGetSymbolAddress((void**)&eo,    g_eo);
    cudaGetSymbolAddress((void**)&dh,    g_dh);
    cudaGetSymbolAddress((void**)&resid, g_resid);
    cudaGetSymbolAddress((void**)&probs, g_probs);
    cudaGetSymbolAddress((void**)&dsv,   g_ds);

    cudaFuncSetAttribute(gemm_mma<0,0>, cudaFuncAttributeMaxDynamicSharedMemorySize, GEMM_SMEM);
    cudaFuncSetAttribute(gemm_mma<0,1>, cudaFuncAttributeMaxDynamicSharedMemorySize, GEMM_SMEM);
    cudaFuncSetAttribute(gemm_mma<1,0>, cudaFuncAttributeMaxDynamicSharedMemorySize, GEMM_SMEM);
    cudaFuncSetAttribute(gemm_fp16,     cudaFuncAttributeMaxDynamicSharedMemorySize, FP16_SMEM);

    // ---- splits of inputs & weights ----
    launch_split(text,  th,  tl,  (u64)NB * FD);
    launch_split(image, ih,  il,  (u64)NB * FD);
    launch_split(Wt,    Wth, Wtl, (u64)PD * FD);
    launch_split(Wi,    Wih, Wil, (u64)PD * FD);
    launch_split(rtW1,  rWh, rWl, (u64)RHD * TWOP);
    launch_split(expW,  eWh, eWl, (u64)NE * HD * TWOP);
    launch_split(dsW1,  dWh, dWl, (u64)HD * TWOP);
    launch_split(outW,  oWh, oWl, (u64)FD * HD);

    // 1) tp = gelu(text @ Wt^T + bt) -> comb[:, 0:512] (split bf16)
    gemm_mma<0,1><<<dim3(PD/256, NB/128), 256, GEMM_SMEM>>>(
        th, tl, Wth, Wtl, nullptr, cbh, cbl, FD, TWOP, 0, bt);
    // 2) ip = gelu(image @ Wi^T + bi) -> comb[:, 512:1024]
    gemm_mma<0,1><<<dim3(PD/256, NB/128), 256, GEMM_SMEM>>>(
        ih, il, Wih, Wil, nullptr, cbh, cbl, FD, TWOP, PD, bi);
    // 3) router hidden = gelu(comb @ rt_W1^T + rt_b1)
    gemm_mma<0,0><<<dim3(RHD/256, NB/128), 256, GEMM_SMEM>>>(
        cbh, cbl, rWh, rWl, rh, nullptr, nullptr, TWOP, RHD, 0, rtb1);
    // 4) router logits + softmax
    router_kernel<<<(NB * 32 + 255) / 256, 256>>>(rh, rtW2, rtb2, probs, out + PR_OFF);
    // 5) expert_out = gelu(comb @ exp_W^T + exp_b)  [B, 4096]
    gemm_mma<0,0><<<dim3((NE*HD)/256, NB/128), 256, GEMM_SMEM>>>(
        cbh, cbl, eWh, eWl, eo, nullptr, nullptr, TWOP, NE*HD, 0, expb);
    // 6) fused hidden (split bf16 out)
    expert_reduce_kernel<<<((u64)NB * HD + 255) / 256, 256>>>(eo, probs, fuh, ful);
    // 7) ds hidden = gelu(comb @ ds_W1^T + ds_b1)
    gemm_mma<0,0><<<dim3(HD/256, NB/128), 256, GEMM_SMEM>>>(
        cbh, cbl, dWh, dWl, dh, nullptr, nullptr, TWOP, HD, 0, dsb1);
    // 8) ds = sigmoid(dh @ ds_W2^T + ds_b2)
    ds_kernel<<<(NB * 32 + 255) / 256, 256>>>(dh, dsW2, dsb2, dsv, out + DS_OFF);
    // 9) residual = fused @ out_W^T + out_b
    gemm_mma<1,0><<<dim3(FD/256, NB/128), 256, GEMM_SMEM>>>(
        fuh, ful, oWh, oWl, resid, nullptr, nullptr, HD, FD, 0, outb);
    // 10) pred = normalize(ds*text + (1-ds)*image + residual) -> fp16
    fuse_norm_kernel<<<NB, 256>>>(resid, text, image, dsv, prf);
    // 11) tgt = normalize(target) -> fp16
    norm_kernel<<<NT, 256>>>(target, tgf);
    // 12) logits = exp(logit_scale) * pred @ tgt^T  (plain fp16, 1 product)
    gemm_fp16<<<dim3(NT/256, NB/128), 256, FP16_SMEM>>>(
        prf, tgf, out, FD, NT, lscale);
}

// round 16
// speedup vs baseline: 1.6213x; 1.6213x over previous
#include <cuda_runtime.h>
#include <cuda_fp16.h>
#include <stdint.h>
#include <math.h>

// ---------------------------------------------------------------------------
// Problem constants
// ---------------------------------------------------------------------------
#define NB   8192
#define NT   8192
#define FD   768
#define PD   512
#define HD   1024
#define NE   4
#define TWOP 1024
#define RHD  256

#define DS_OFF  (8192ull*8192ull)
#define PR_OFF  (8192ull*8192ull + 8192ull)

typedef unsigned long long u64;

// ---------------------------------------------------------------------------
// Scratch (device globals: allocation-free), all-fp16 operand arrays
// ---------------------------------------------------------------------------
__device__ __half g_tf  [8192ull*768];     // text fp16
__device__ __half g_imf [8192ull*768];     // image fp16
__device__ __half g_Wtf [512*768];
__device__ __half g_Wif [512*768];
__device__ __half g_rWf [256*1024];
__device__ __half g_eWf [4096ull*1024];
__device__ __half g_dWf [1024ull*1024];
__device__ __half g_oWf [768*1024];
__device__ __half g_cbf [8192ull*1024];    // comb fp16
__device__ __half g_fuf [8192ull*1024];    // fused hidden fp16
__device__ __half g_prf [8192ull*768];     // pred fp16
__device__ __half g_tgf [8192ull*768];     // tgt fp16
__device__ float g_rh   [8192ull*256];
__device__ float g_eo   [8192ull*4096];
__device__ float g_dh   [8192ull*1024];
__device__ float g_resid[8192ull*768];
__device__ float g_probs[8192ull*4];
__device__ float g_ds   [8192];

// ---------------------------------------------------------------------------
// Generic-ISA helpers (sm_80-level: ldmatrix / mma.sync / cp.async only)
// ---------------------------------------------------------------------------
__device__ __forceinline__ uint32_t smem_u32(const void* p) {
    uint32_t a;
    asm("{ .reg .u64 t; cvta.to.shared.u64 t, %1; cvt.u32.u64 %0, t; }"
        : "=r"(a) : "l"(p));
    return a;
}

__device__ __forceinline__ void ldsm4(uint32_t* r, uint32_t addr) {
    asm volatile("ldmatrix.sync.aligned.m8n8.x4.shared.b16 {%0,%1,%2,%3}, [%4];"
        : "=r"(r[0]), "=r"(r[1]), "=r"(r[2]), "=r"(r[3]) : "r"(addr));
}

__device__ __forceinline__ void mma16816h(float* c, const uint32_t* a, const uint32_t* b) {
    asm volatile(
        "mma.sync.aligned.m16n8k16.row.col.f32.f16.f16.f32 "
        "{%0,%1,%2,%3},{%4,%5,%6,%7},{%8,%9},{%0,%1,%2,%3};"
        : "+f"(c[0]), "+f"(c[1]), "+f"(c[2]), "+f"(c[3])
        : "r"(a[0]), "r"(a[1]), "r"(a[2]), "r"(a[3]), "r"(b[0]), "r"(b[1]));
}

__device__ __forceinline__ void cp16(uint32_t saddr, const void* gptr) {
    asm volatile("cp.async.cg.shared.global [%0], [%1], 16;"
        :: "r"(saddr), "l"(gptr));
}
#define CP_COMMIT() asm volatile("cp.async.commit_group;")
#define CP_WAIT0()  asm volatile("cp.async.wait_group 0;")
#define CP_WAIT1()  asm volatile("cp.async.wait_group 1;")

__device__ __forceinline__ float gelu_exact(float x) {
    return 0.5f * x * (1.0f + erff(x * 0.70710678118654752440f));
}

// ---------------------------------------------------------------------------
// fp16 HMMA GEMM: C[M,N] = epi( A[M,K] @ B[N,K]^T ), fp32 accumulate.
// CTA 128x256, 8 warps (warp tile 64x64, grid 2x4), BK=32,
// cp.async 3-stage pipeline (wait_group 1 steady-state).
// Smem per buffer (24KB): A@0(8K) B@8K(16K).
// Row = 64B (32 fp16), 16B-chunk swizzle: chunk' = chunk ^ ((row>>1)&3).
// EPI: 0 = gelu(acc+bias[n]), 1 = acc+bias[n], 2 = exp(*scale_p)*acc
// OUT: 0 = fp32 C, 1 = fp16 Cf
// ---------------------------------------------------------------------------
#define BUFSZ 24576
#define GEMM_SMEM (3 * BUFSZ + 128)

template <int EPI, int OUT>
__global__ __launch_bounds__(256, 1) void gemm_f16(
    const __half* __restrict__ A, const __half* __restrict__ B,
    float* __restrict__ C, __half* __restrict__ Cf,
    int K, int ldc, int coloff,
    const float* __restrict__ bias, const float* __restrict__ scale_p)
{
    extern __shared__ char smraw[];
    const uint32_t sbase = (smem_u32(smraw) + 127u) & ~127u;

    const int tid  = threadIdx.x;
    const int wid  = tid >> 5;
    const int lane = tid & 31;
    const int wm   = wid >> 2;       // 0..1  (M: 64 rows)
    const int wn   = wid & 3;        // 0..3  (N: 64 cols)
    const int bm   = blockIdx.y * 128;
    const int bn   = blockIdx.x * 256;

    float acc[4][8][4];
    #pragma unroll
    for (int i = 0; i < 4; i++)
        #pragma unroll
        for (int j = 0; j < 8; j++)
            #pragma unroll
            for (int r = 0; r < 4; r++) acc[i][j][r] = 0.f;

    const __half* srcA = A + (u64)bm * K;
    const __half* srcB = B + (u64)bn * K;

    const int srow = tid >> 2;
    const int sc   = tid & 3;
    const uint32_t sw0 = (uint32_t)(srow * 64 + ((sc ^ ((srow >> 1) & 3)) << 4));
    const int gcol = sc * 8;

    const int rA  = lane & 15;
    const int cAx = (lane >> 4) & 1;
    const int nB  = (lane & 7) | (((lane >> 4) & 1) << 3);
    const int cBx = (lane >> 3) & 1;

    const int nchunk = K >> 5;

#define LOAD_CHUNK(KB, BUFB) do {                                                   \
        const int _kb = (KB); const uint32_t _bb = (BUFB);                          \
        _Pragma("unroll")                                                           \
        for (int p = 0; p < 2; p++)                                                 \
            cp16(_bb + p * 4096 + sw0, srcA + (u64)(srow + p * 64) * K + _kb + gcol); \
        _Pragma("unroll")                                                           \
        for (int p = 0; p < 4; p++)                                                 \
            cp16(_bb + 8192 + p * 4096 + sw0, srcB + (u64)(srow + p * 64) * K + _kb + gcol); \
        CP_COMMIT();                                                                \
    } while (0)

    LOAD_CHUNK(0, sbase);
    if (nchunk > 1) LOAD_CHUNK(32, sbase + BUFSZ);

    for (int i = 0; i < nchunk; i++) {
        if (i == nchunk - 1) { CP_WAIT0(); } else { CP_WAIT1(); }
        __syncthreads();
        if (i + 2 < nchunk)
            LOAD_CHUNK((i + 2) << 5, sbase + (uint32_t)(((i + 2) % 3) * BUFSZ));

        const uint32_t bufb = sbase + (uint32_t)((i % 3) * BUFSZ);
        #pragma unroll
        for (int ks = 0; ks < 2; ks++) {
            uint32_t a[4][4], bb[8][2], t4[4];
            #pragma unroll
            for (int am = 0; am < 4; am++) {
                const int row = wm * 64 + am * 16 + rA;
                const int c   = ks * 2 + cAx;
                ldsm4(a[am], bufb + row * 64 + (uint32_t)((c ^ ((row >> 1) & 3)) << 4));
            }
            #pragma unroll
            for (int np = 0; np < 4; np++) {
                const int row = wn * 64 + np * 16 + nB;
                const int c   = ks * 2 + cBx;
                ldsm4(t4, bufb + 8192 + row * 64 + (uint32_t)((c ^ ((row >> 1) & 3)) << 4));
                bb[np*2][0] = t4[0]; bb[np*2][1] = t4[1];
                bb[np*2+1][0] = t4[2]; bb[np*2+1][1] = t4[3];
            }
            #pragma unroll
            for (int am = 0; am < 4; am++)
                #pragma unroll
                for (int an = 0; an < 8; an++)
                    mma16816h(acc[am][an], a[am], bb[an]);
        }
        __syncthreads();
    }
#undef LOAD_CHUNK

    float scale = 1.0f;
    if (EPI == 2) scale = expf(*scale_p);
    const int g  = lane >> 2;
    const int tg = lane & 3;
    #pragma unroll
    for (int am = 0; am < 4; am++) {
        const int row0 = bm + wm * 64 + am * 16 + g;
        #pragma unroll
        for (int an = 0; an < 8; an++) {
            const int coln = wn * 64 + an * 8 + tg * 2;
            float v[4];
            #pragma unroll
            for (int r = 0; r < 4; r++) {
                float x = acc[am][an][r];
                const int n = bn + coln + (r & 1);
                if (EPI == 0)      x = gelu_exact(x + __ldg(bias + n));
                else if (EPI == 1) x = x + __ldg(bias + n);
                else               x = x * scale;
                v[r] = x;
            }
            if (OUT == 0) {
                *(float2*)(C + (u64)row0 * ldc + coloff + bn + coln)       = make_float2(v[0], v[1]);
                *(float2*)(C + (u64)(row0 + 8) * ldc + coloff + bn + coln) = make_float2(v[2], v[3]);
            } else {
                __half2 h0; h0.x = __float2half(v[0]); h0.y = __float2half(v[1]);
                __half2 h1; h1.x = __float2half(v[2]); h1.y = __float2half(v[3]);
                *(__half2*)(Cf + (u64)row0 * ldc + coloff + bn + coln)       = h0;
                *(__half2*)(Cf + (u64)(row0 + 8) * ldc + coloff + bn + coln) = h1;
            }
        }
    }
}

// ---------------------------------------------------------------------------
// fp32 -> fp16 convert, vectorized x4
// ---------------------------------------------------------------------------
__global__ void conv_kernel(const float* __restrict__ in,
                            __half* __restrict__ outp, int n4)
{
    int i = blockIdx.x * blockDim.x + threadIdx.x;
    if (i >= n4) return;
    float4 v = ((const float4*)in)[i];
    __half2 h0; h0.x = __float2half(v.x); h0.y = __float2half(v.y);
    __half2 h1; h1.x = __float2half(v.z); h1.y = __float2half(v.w);
    ((__half2*)outp)[2*i]   = h0;
    ((__half2*)outp)[2*i+1] = h1;
}

// ---------------------------------------------------------------------------
// Router: logits = rh @ rt_W2^T + b2 ; softmax. One warp per row.
// ---------------------------------------------------------------------------
__global__ void router_kernel(const float* __restrict__ rh,
                              const float* __restrict__ W2,
                              const float* __restrict__ b2,
                              float* __restrict__ probs,
                              float* __restrict__ out_probs)
{
    int warp = (blockIdx.x * blockDim.x + threadIdx.x) >> 5;
    int lane = threadIdx.x & 31;
    if (warp >= NB) return;
    const float* r = rh + (u64)warp * RHD;
    float s0 = 0.f, s1 = 0.f, s2 = 0.f, s3 = 0.f;
    #pragma unroll
    for (int i = 0; i < RHD / 32; i++) {
        int c = lane + i * 32;
        float v = r[c];
        s0 += v * W2[c];
        s1 += v * W2[RHD + c];
        s2 += v * W2[2 * RHD + c];
        s3 += v * W2[3 * RHD + c];
    }
    #pragma unroll
    for (int o = 16; o > 0; o >>= 1) {
        s0 += __shfl_xor_sync(0xffffffffu, s0, o);
        s1 += __shfl_xor_sync(0xffffffffu, s1, o);
        s2 += __shfl_xor_sync(0xffffffffu, s2, o);
        s3 += __shfl_xor_sync(0xffffffffu, s3, o);
    }
    if (lane == 0) {
        float l0 = s0 + b2[0], l1 = s1 + b2[1], l2 = s2 + b2[2], l3 = s3 + b2[3];
        float m  = fmaxf(fmaxf(l0, l1), fmaxf(l2, l3));
        float e0 = expf(l0 - m), e1 = expf(l1 - m), e2 = expf(l2 - m), e3 = expf(l3 - m);
        float inv = 1.f / (e0 + e1 + e2 + e3);
        float4 p = make_float4(e0 * inv, e1 * inv, e2 * inv, e3 * inv);
        *(float4*)(probs + (u64)warp * 4) = p;
        *(float4*)(out_probs + (u64)warp * 4) = p;
    }
}

// ---------------------------------------------------------------------------
// ds = sigmoid(dh . W2 + b2). One warp per row.
// ---------------------------------------------------------------------------
__global__ void ds_kernel(const float* __restrict__ dh,
                          const float* __restrict__ W2,
                          const float* __restrict__ b2,
                          float* __restrict__ ds,
                          float* __restrict__ out_ds)
{
    int warp = (blockIdx.x * blockDim.x + threadIdx.x) >> 5;
    int lane = threadIdx.x & 31;
    if (warp >= NB) return;
    const float* r = dh + (u64)warp * HD;
    float s = 0.f;
    #pragma unroll
    for (int i = 0; i < HD / 32; i++) s += r[lane + i * 32] * W2[lane + i * 32];
    #pragma unroll
    for (int o = 16; o > 0; o >>= 1) s += __shfl_xor_sync(0xffffffffu, s, o);
    if (lane == 0) {
        float sg = 1.f / (1.f + expf(-(s + b2[0])));
        ds[warp] = sg;
        out_ds[warp] = sg;
    }
}

// ---------------------------------------------------------------------------
// fused[b,h] = sum_e probs[b,e]*eo[b,e*H+h] -> fp16 out
// ---------------------------------------------------------------------------
__global__ void expert_reduce_kernel(const float* __restrict__ eo,
                                     const float* __restrict__ probs,
                                     __half* __restrict__ ff)
{
    u64 idx = (u64)blockIdx.x * blockDim.x + threadIdx.x;
    if (idx >= (u64)NB * HD) return;
    u64 b = idx >> 10;
    u64 h = idx & 1023u;
    const float* p = probs + b * 4;
    const float* e = eo + b * (u64)(NE * HD) + h;
    float v = p[0]*e[0] + p[1]*e[HD] + p[2]*e[2*HD] + p[3]*e[3*HD];
    ff[idx] = __float2half(v);
}

// ---------------------------------------------------------------------------
// pred = normalize(ds*text + (1-ds)*image + resid) -> fp16
// ---------------------------------------------------------------------------
__global__ __launch_bounds__(256) void fuse_norm_kernel(
    const float* __restrict__ resid, const float* __restrict__ text,
    const float* __restrict__ image, const float* __restrict__ ds,
    __half* __restrict__ pf)
{
    __shared__ float red[8];
    const int b = blockIdx.x;
    const int t = threadIdx.x;
    const float d = ds[b];
    float v[3];
    float ss = 0.f;
    #pragma unroll
    for (int q = 0; q < 3; q++) {
        u64 off = (u64)b * FD + t + q * 256;
        float val = d * text[off] + (1.f - d) * image[off] + resid[off];
        v[q] = val;
        ss += val * val;
    }
    #pragma unroll
    for (int o = 16; o > 0; o >>= 1) ss += __shfl_xor_sync(0xffffffffu, ss, o);
    if ((t & 31) == 0) red[t >> 5] = ss;
    __syncthreads();
    if (t < 32) {
        float x = (t < 8) ? red[t] : 0.f;
        #pragma unroll
        for (int o = 4; o > 0; o >>= 1) x += __shfl_xor_sync(0xffffffffu, x, o);
        if (t == 0) red[0] = x;
    }
    __syncthreads();
    const float inv = 1.f / fmaxf(sqrtf(red[0]), 1e-12f);
    #pragma unroll
    for (int q = 0; q < 3; q++) {
        u64 off = (u64)b * FD + t + q * 256;
        pf[off] = __float2half(v[q] * inv);
    }
}

// ---------------------------------------------------------------------------
// tgt = normalize(target) -> fp16
// ---------------------------------------------------------------------------
__global__ __launch_bounds__(256) void norm_kernel(const float* __restrict__ in,
                                                   __half* __restrict__ tf)
{
    __shared__ float red[8];
    const int b = blockIdx.x;
    const int t = threadIdx.x;
    float v[3];
    float ss = 0.f;
    #pragma unroll
    for (int q = 0; q < 3; q++) {
        float val = in[(u64)b * FD + t + q * 256];
        v[q] = val;
        ss += val * val;
    }
    #pragma unroll
    for (int o = 16; o > 0; o >>= 1) ss += __shfl_xor_sync(0xffffffffu, ss, o);
    if ((t & 31) == 0) red[t >> 5] = ss;
    __syncthreads();
    if (t < 32) {
        float x = (t < 8) ? red[t] : 0.f;
        #pragma unroll
        for (int o = 4; o > 0; o >>= 1) x += __shfl_xor_sync(0xffffffffu, x, o);
        if (t == 0) red[0] = x;
    }
    __syncthreads();
    const float inv = 1.f / fmaxf(sqrtf(red[0]), 1e-12f);
    #pragma unroll
    for (int q = 0; q < 3; q++) {
        u64 off = (u64)b * FD + t + q * 256;
        tf[off] = __float2half(v[q] * inv);
    }
}

// ---------------------------------------------------------------------------
// Launch
// ---------------------------------------------------------------------------
static inline void launch_conv(const float* src, __half* dst, u64 n) {
    int n4 = (int)(n >> 2);
    conv_kernel<<<(n4 + 255) / 256, 256>>>(src, dst, n4);
}

extern "C" void kernel_launch(void* const* d_in, const int* in_sizes, int n_in,
                              void* d_out, int out_size)
{
    const float* image  = (const float*)d_in[0];
    const float* text   = (const float*)d_in[1];
    const float* target = (const float*)d_in[2];
    const float* Wt     = (const float*)d_in[3];
    const float* bt     = (const float*)d_in[4];
    const float* Wi     = (const float*)d_in[5];
    const float* bi     = (const float*)d_in[6];
    const float* dsW1   = (const float*)d_in[7];
    const float* dsb1   = (const float*)d_in[8];
    const float* dsW2   = (const float*)d_in[9];
    const float* dsb2   = (const float*)d_in[10];
    const float* expW   = (const float*)d_in[11];
    const float* expb   = (const float*)d_in[12];
    const float* rtW1   = (const float*)d_in[13];
    const float* rtb1   = (const float*)d_in[14];
    const float* rtW2   = (const float*)d_in[15];
    const float* rtb2   = (const float*)d_in[16];
    const float* outW   = (const float*)d_in[17];
    const float* outb   = (const float*)d_in[18];
    const float* lscale = (const float*)d_in[19];
    float* out = (float*)d_out;

    __half *tf,*imf,*Wtf,*Wif,*rWf,*eWf,*dWf,*oWf,*cbf,*fuf,*prf,*tgf;
    float *rh,*eo,*dh,*resid,*probs,*dsv;
    cudaGetSymbolAddress((void**)&tf,  g_tf);  cudaGetSymbolAddress((void**)&imf, g_imf);
    cudaGetSymbolAddress((void**)&Wtf, g_Wtf); cudaGetSymbolAddress((void**)&Wif, g_Wif);
    cudaGetSymbolAddress((void**)&rWf, g_rWf); cudaGetSymbolAddress((void**)&eWf, g_eWf);
    cudaGetSymbolAddress((void**)&dWf, g_dWf); cudaGetSymbolAddress((void**)&oWf, g_oWf);
    cudaGetSymbolAddress((void**)&cbf, g_cbf); cudaGetSymbolAddress((void**)&fuf, g_fuf);
    cudaGetSymbolAddress((void**)&prf, g_prf); cudaGetSymbolAddress((void**)&tgf, g_tgf);
    cudaGetSymbolAddress((void**)&rh,    g_rh);
    cudaGetSymbolAddress((void**)&eo,    g_eo);
    cudaGetSymbolAddress((void**)&dh,    g_dh);
    cudaGetSymbolAddress((void**)&resid, g_resid);
    cudaGetSymbolAddress((void**)&probs, g_probs);
    cudaGetSymbolAddress((void**)&dsv,   g_ds);

    cudaFuncSetAttribute(gemm_f16<0,0>, cudaFuncAttributeMaxDynamicSharedMemorySize, GEMM_SMEM);
    cudaFuncSetAttribute(gemm_f16<0,1>, cudaFuncAttributeMaxDynamicSharedMemorySize, GEMM_SMEM);
    cudaFuncSetAttribute(gemm_f16<1,0>, cudaFuncAttributeMaxDynamicSharedMemorySize, GEMM_SMEM);
    cudaFuncSetAttribute(gemm_f16<2,0>, cudaFuncAttributeMaxDynamicSharedMemorySize, GEMM_SMEM);

    // ---- fp32 -> fp16 conversions ----
    launch_conv(text,  tf,  (u64)NB * FD);
    launch_conv(image, imf, (u64)NB * FD);
    launch_conv(Wt,    Wtf, (u64)PD * FD);
    launch_conv(Wi,    Wif, (u64)PD * FD);
    launch_conv(rtW1,  rWf, (u64)RHD * TWOP);
    launch_conv(expW,  eWf, (u64)NE * HD * TWOP);
    launch_conv(dsW1,  dWf, (u64)HD * TWOP);
    launch_conv(outW,  oWf, (u64)FD * HD);

    // 1) tp = gelu(text @ Wt^T + bt) -> comb[:, 0:512] (fp16)
    gemm_f16<0,1><<<dim3(PD/256, NB/128), 256, GEMM_SMEM>>>(
        tf, Wtf, nullptr, cbf, FD, TWOP, 0, bt, nullptr);
    // 2) ip = gelu(image @ Wi^T + bi) -> comb[:, 512:1024]
    gemm_f16<0,1><<<dim3(PD/256, NB/128), 256, GEMM_SMEM>>>(
        imf, Wif, nullptr, cbf, FD, TWOP, PD, bi, nullptr);
    // 3) router hidden = gelu(comb @ rt_W1^T + rt_b1)
    gemm_f16<0,0><<<dim3(RHD/256, NB/128), 256, GEMM_SMEM>>>(
        cbf, rWf, rh, nullptr, TWOP, RHD, 0, rtb1, nullptr);
    // 4) router logits + softmax
    router_kernel<<<(NB * 32 + 255) / 256, 256>>>(rh, rtW2, rtb2, probs, out + PR_OFF);
    // 5) expert_out = gelu(comb @ exp_W^T + exp_b)  [B, 4096]
    gemm_f16<0,0><<<dim3((NE*HD)/256, NB/128), 256, GEMM_SMEM>>>(
        cbf, eWf, eo, nullptr, TWOP, NE*HD, 0, expb, nullptr);
    // 6) fused hidden (fp16 out)
    expert_reduce_kernel<<<((u64)NB * HD + 255) / 256, 256>>>(eo, probs, fuf);
    // 7) ds hidden = gelu(comb @ ds_W1^T + ds_b1)
    gemm_f16<0,0><<<dim3(HD/256, NB/128), 256, GEMM_SMEM>>>(
        cbf, dWf, dh, nullptr, TWOP, HD, 0, dsb1, nullptr);
    // 8) ds = sigmoid(dh @ ds_W2^T + ds_b2)
    ds_kernel<<<(NB * 32 + 255) / 256, 256>>>(dh, dsW2, dsb2, dsv, out + DS_OFF);
    // 9) residual = fused @ out_W^T + out_b
    gemm_f16<1,0><<<dim3(FD/256, NB/128), 256, GEMM_SMEM>>>(
        fuf, oWf, resid, nullptr, HD, FD, 0, outb, nullptr);
    // 10) pred = normalize(ds*text + (1-ds)*image + residual) -> fp16
    fuse_norm_kernel<<<NB, 256>>>(resid, text, image, dsv, prf);
    // 11) tgt = normalize(target) -> fp16
    norm_kernel<<<NT, 256>>>(target, tgf);
    // 12) logits = exp(logit_scale) * pred @ tgt^T
    gemm_f16<2,0><<<dim3(NT/256, NB/128), 256, GEMM_SMEM>>>(
        prf, tgf, out, nullptr, FD, NT, 0, nullptr, lscale);
}